// round 12
// baseline (speedup 1.0000x reference)
#include <cuda_runtime.h>

#define BB 256
#define TT 256
#define DD 128
#define HHH 256

typedef unsigned long long u64t;
typedef unsigned int u32t;

// Blackwell packed fp32 ops (PTX-only; ptxas won't emit FFMA2 from C++)
#define FMA2(d,a,b,c) asm("fma.rn.f32x2 %0, %1, %2, %3;" : "=l"(d) : "l"(a), "l"(b), "l"(c))
#define PACK1(d,x)    asm("mov.b64 %0, {%1, %1};" : "=l"(d) : "r"(x))
#define UNPK(lo,hi,v) asm("mov.b64 {%0, %1}, %2;" : "=r"(lo), "=r"(hi) : "l"(v))

// ---------------- scratch (device globals; no allocations) ----------------
// x_proj buffers are GATE-INTERLEAVED: col = neuron*4 + gate (i,f,g,o)
__device__ float g_xproj_enc[(size_t)BB * TT * 4 * HHH];  // 256 MB
__device__ float g_xproj_dec[(size_t)BB * TT * 4 * DD];   // 128 MB
__device__ float g_enc_out[(size_t)BB * TT * HHH];        // 64 MB
__device__ float g_hbuf_enc[2][BB][HHH];
__device__ float g_hbuf_dec[2][BB][DD];
__device__ int g_ctr_enc[TT][4];   // per-step, per-btile (32-CTA groups)
__device__ int g_ctr_dec[TT][4];

// ---------------- init: zero h0 buffers + barrier counters ----------------
__global__ void init_kernel() {
    int tid = blockIdx.x * blockDim.x + threadIdx.x;
    int stride = gridDim.x * blockDim.x;
    float* he = &g_hbuf_enc[0][0][0];
    float* hd = &g_hbuf_dec[0][0][0];
    for (int i = tid; i < 2 * BB * HHH; i += stride) he[i] = 0.f;
    for (int i = tid; i < 2 * BB * DD; i += stride) hd[i] = 0.f;
    int* ce = &g_ctr_enc[0][0];
    int* cd = &g_ctr_dec[0][0];
    for (int i = tid; i < TT * 4; i += stride) { ce[i] = 0; cd[i] = 0; }
}

// ---------------- input-projection GEMM: C[M,N] = A[M,K] @ W[N,K]^T + b1 + b2
// 128x128 tiles, BK=8, 256 threads, 8x8 micro-tile, packed f32x2 FMA.
// Output stored gate-interleaved: out_col = (c & (Hn-1))*4 + (c >> SHIFT).
template <int K, int SHIFT>
__global__ __launch_bounds__(256) void proj_kernel(
    const float* __restrict__ Ain, const float* __restrict__ W,
    const float* __restrict__ b1, const float* __restrict__ b2,
    int src_sel, int dst_sel, int N)
{
    const float* A = src_sel ? (const float*)g_enc_out : Ain;
    float* C = dst_sel ? (float*)g_xproj_dec : (float*)g_xproj_enc;
    const int HMASK = (1 << SHIFT) - 1;

    __shared__ float As[8][128];
    __shared__ float Bs[8][128];
    int tid = threadIdx.x;
    int bn = blockIdx.x, bm = blockIdx.y;
    int tr = tid >> 4, tc = tid & 15;   // 16x16 thread grid
    int lr = tid >> 1;                  // stage row 0..127
    int lk = (tid & 1) << 2;            // 0 or 4

    const float* Ag = A + (size_t)(bm * 128 + lr) * K + lk;
    const float* Wg = W + (size_t)(bn * 128 + lr) * K + lk;

    u64t acc[8][4];
#pragma unroll
    for (int i = 0; i < 8; ++i)
#pragma unroll
        for (int j = 0; j < 4; ++j) acc[i][j] = 0ULL;

    for (int kb = 0; kb < K; kb += 8) {
        float4 av = *(const float4*)(Ag + kb);
        float4 wv = *(const float4*)(Wg + kb);
        __syncthreads();
        As[lk + 0][lr] = av.x; As[lk + 1][lr] = av.y;
        As[lk + 2][lr] = av.z; As[lk + 3][lr] = av.w;
        Bs[lk + 0][lr] = wv.x; Bs[lk + 1][lr] = wv.y;
        Bs[lk + 2][lr] = wv.z; Bs[lk + 3][lr] = wv.w;
        __syncthreads();
#pragma unroll
        for (int kk = 0; kk < 8; ++kk) {
            float4 alo = *(const float4*)&As[kk][tr * 4];
            float4 ahi = *(const float4*)&As[kk][64 + tr * 4];
            ulonglong2 wlo = *(const ulonglong2*)&Bs[kk][tc * 4];
            ulonglong2 whi = *(const ulonglong2*)&Bs[kk][64 + tc * 4];
            float ar[8] = {alo.x, alo.y, alo.z, alo.w, ahi.x, ahi.y, ahi.z, ahi.w};
#pragma unroll
            for (int i = 0; i < 8; ++i) {
                u64t a2; PACK1(a2, __float_as_uint(ar[i]));
                FMA2(acc[i][0], a2, wlo.x, acc[i][0]);
                FMA2(acc[i][1], a2, wlo.y, acc[i][1]);
                FMA2(acc[i][2], a2, whi.x, acc[i][2]);
                FMA2(acc[i][3], a2, whi.y, acc[i][3]);
            }
        }
    }
    int c_lo = bn * 128 + tc * 4;
    int c_hi = c_lo + 64;
    float4 v1 = *(const float4*)&b1[c_lo];
    float4 v2 = *(const float4*)&b2[c_lo];
    float4 blo = make_float4(v1.x + v2.x, v1.y + v2.y, v1.z + v2.z, v1.w + v2.w);
    float4 u1 = *(const float4*)&b1[c_hi];
    float4 u2 = *(const float4*)&b2[c_hi];
    float4 bhi = make_float4(u1.x + u2.x, u1.y + u2.y, u1.z + u2.z, u1.w + u2.w);
#pragma unroll
    for (int i = 0; i < 8; ++i) {
        int row = bm * 128 + (i < 4 ? tr * 4 + i : 64 + tr * 4 + (i - 4));
        float* Crow = C + (size_t)row * N;
        u32t l0, h0, l1, h1;
        UNPK(l0, h0, acc[i][0]); UNPK(l1, h1, acc[i][1]);
        float v[4] = {__uint_as_float(l0) + blo.x, __uint_as_float(h0) + blo.y,
                      __uint_as_float(l1) + blo.z, __uint_as_float(h1) + blo.w};
#pragma unroll
        for (int j = 0; j < 4; ++j) {
            int c = c_lo + j;
            Crow[((c & HMASK) << 2) | (c >> SHIFT)] = v[j];
        }
        UNPK(l0, h0, acc[i][2]); UNPK(l1, h1, acc[i][3]);
        float u[4] = {__uint_as_float(l0) + bhi.x, __uint_as_float(h0) + bhi.y,
                      __uint_as_float(l1) + bhi.z, __uint_as_float(h1) + bhi.w};
#pragma unroll
        for (int j = 0; j < 4; ++j) {
            int c = c_hi + j;
            Crow[((c & HMASK) << 2) | (c >> SHIFT)] = u[j];
        }
    }
}

// ---------------- encoder recurrence: persistent, 128 CTAs ----------------
// CTA = 64 batch rows x 8 neurons. Thread = 2 rows x 1 neuron (all 4 gates).
// Whh in smem once (gate-interleaved cols). c-state in registers. No Gs/Cs.
#define ENC_SMEM_BYTES ((8192 + 16640) * 4)

__global__ __launch_bounds__(256) void enc_rec_kernel(const float* __restrict__ Whh)
{
    extern __shared__ float sm[];
    float (*Ws)[32]  = (float(*)[32])sm;           // [k][c], c = jj*4 + gate
    float (*Hs)[260] = (float(*)[260])(sm + 8192); // [row][k]

    int tid = threadIdx.x;
    int slice = blockIdx.x & 31;   // neuron slices of 8
    int btile = blockIdx.x >> 5;   // batch tiles of 64
    int b0 = btile * 64;
    int j0 = slice * 8;

    { // Ws fill: col c = jj*4 + gate  ->  Whh row gate*HHH + (j0+jj)
        int c = tid & 31;
        int k0 = (tid >> 5) << 5;
        int grow = (c & 3) * HHH + j0 + (c >> 2);
        const float* src = Whh + (size_t)grow * HHH + k0;
#pragma unroll
        for (int kk = 0; kk < 32; ++kk) Ws[k0 + kk][c] = src[kk];
    }
    __syncthreads();

    const int tr2 = (tid >> 3) << 1;   // row pair 0..62
    const int tc  = tid & 7;           // neuron index within slice
    const int jn  = j0 + tc;           // global neuron 0..255
    const float* hr0 = &Hs[tr2][0];
    const float* hr1 = &Hs[tr2 + 1][0];
    const float* wcol = &Ws[0][tc * 4];

    float c0 = 0.f, c1 = 0.f;

    for (int t = 0; t < TT; ++t) {
        // issue x_proj loads first (independent of barrier/staging)
        const float* xp0 = &g_xproj_enc[((size_t)(b0 + tr2) * TT + t) * 1024 + (jn << 2)];
        ulonglong2 q0 = *(const ulonglong2*)xp0;
        ulonglong2 q1 = *(const ulonglong2*)(xp0 + (size_t)TT * 1024);

        { // stage h_prev tile [64][256]
            int r = tid >> 2;
            int k0 = (tid & 3) << 6;
            const float* hp = &g_hbuf_enc[t & 1][b0 + r][k0];
            float* dst = &Hs[r][k0];
#pragma unroll
            for (int kk = 0; kk < 64; kk += 4)
                *(float4*)(dst + kk) = *(const float4*)(hp + kk);
        }
        __syncthreads();

        u64t Aif0 = q0.x, Ago0 = q0.y, Aif1 = q1.x, Ago1 = q1.y;
#pragma unroll 8
        for (int k = 0; k < HHH; ++k) {
            u64t H0, H1;
            PACK1(H0, __float_as_uint(hr0[k]));
            PACK1(H1, __float_as_uint(hr1[k]));
            ulonglong2 w = *(const ulonglong2*)(wcol + (k << 5));
            FMA2(Aif0, H0, w.x, Aif0); FMA2(Ago0, H0, w.y, Ago0);
            FMA2(Aif1, H1, w.x, Aif1); FMA2(Ago1, H1, w.y, Ago1);
        }

        // in-register LSTM epilogue (all 4 gates live in this thread)
        float h0v, h1v;
        {
            u32t ui, uf, ug, uo;
            UNPK(ui, uf, Aif0); UNPK(ug, uo, Ago0);
            float si = 1.f / (1.f + __expf(-__uint_as_float(ui)));
            float sf = 1.f / (1.f + __expf(-__uint_as_float(uf)));
            float tg = tanhf(__uint_as_float(ug));
            float so = 1.f / (1.f + __expf(-__uint_as_float(uo)));
            c0 = fmaf(sf, c0, si * tg);
            h0v = so * tanhf(c0);
        }
        {
            u32t ui, uf, ug, uo;
            UNPK(ui, uf, Aif1); UNPK(ug, uo, Ago1);
            float si = 1.f / (1.f + __expf(-__uint_as_float(ui)));
            float sf = 1.f / (1.f + __expf(-__uint_as_float(uf)));
            float tg = tanhf(__uint_as_float(ug));
            float so = 1.f / (1.f + __expf(-__uint_as_float(uo)));
            c1 = fmaf(sf, c1, si * tg);
            h1v = so * tanhf(c1);
        }
        g_hbuf_enc[(t + 1) & 1][b0 + tr2][jn] = h0v;
        g_hbuf_enc[(t + 1) & 1][b0 + tr2 + 1][jn] = h1v;

        __syncthreads();                      // all h stores issued
        int* ctr = &g_ctr_enc[t][btile];
        if (tid == 0) { __threadfence(); atomicAdd(ctr, 1); }  // single-thread release
        // deferred enc_out stores overlap the spin
        g_enc_out[((size_t)(b0 + tr2) * TT + t) * HHH + jn] = h0v;
        g_enc_out[((size_t)(b0 + tr2 + 1) * TT + t) * HHH + jn] = h1v;
        if (tid == 0) {
            while (*(volatile int*)ctr < 32) { }   // busy poll, no nanosleep
            __threadfence();                        // single-thread acquire
        }
        __syncthreads();
    }
}

// ---------------- decoder recurrence: 128 CTAs, thread = 1 row x 1 neuron --
__global__ __launch_bounds__(256) void dec_rec_kernel(
    const float* __restrict__ Whh, float* __restrict__ out)
{
    __shared__ float Ws[128][16];   // [k][c], c = jj*4 + gate
    __shared__ float Hs[64][132];

    int tid = threadIdx.x;
    int slice = blockIdx.x & 31;   // neuron slices of 4
    int btile = blockIdx.x >> 5;
    int b0 = btile * 64;
    int j0 = slice * 4;

    { // Ws fill: c = jj*4 + gate -> Whh row gate*DD + (j0+jj)
        int c = tid & 15;
        int k0 = (tid >> 4) << 3;
        int grow = (c & 3) * DD + j0 + (c >> 2);
        const float* src = Whh + (size_t)grow * DD + k0;
#pragma unroll
        for (int kk = 0; kk < 8; ++kk) Ws[k0 + kk][c] = src[kk];
    }
    __syncthreads();

    const int r  = tid >> 2;       // row 0..63
    const int jj = tid & 3;        // neuron within slice
    const int jn = j0 + jj;        // global neuron 0..127
    const float* hr = &Hs[r][0];
    const float* wcol = &Ws[0][jj * 4];

    float cc = 0.f;

    for (int t = 0; t < TT; ++t) {
        const float* xp = &g_xproj_dec[((size_t)(b0 + r) * TT + t) * 512 + (jn << 2)];
        ulonglong2 q = *(const ulonglong2*)xp;

        { // stage h_prev tile [64][128]
            int rr = tid >> 2;
            int k0 = (tid & 3) << 5;
            const float* hp = &g_hbuf_dec[t & 1][b0 + rr][k0];
            float* dst = &Hs[rr][k0];
#pragma unroll
            for (int kk = 0; kk < 32; kk += 4)
                *(float4*)(dst + kk) = *(const float4*)(hp + kk);
        }
        __syncthreads();

        u64t Aif = q.x, Ago = q.y;
#pragma unroll 8
        for (int k = 0; k < DD; ++k) {
            u64t H;
            PACK1(H, __float_as_uint(hr[k]));
            ulonglong2 w = *(const ulonglong2*)(wcol + (k << 4));
            FMA2(Aif, H, w.x, Aif);
            FMA2(Ago, H, w.y, Ago);
        }

        float hv;
        {
            u32t ui, uf, ug, uo;
            UNPK(ui, uf, Aif); UNPK(ug, uo, Ago);
            float si = 1.f / (1.f + __expf(-__uint_as_float(ui)));
            float sf = 1.f / (1.f + __expf(-__uint_as_float(uf)));
            float tg = tanhf(__uint_as_float(ug));
            float so = 1.f / (1.f + __expf(-__uint_as_float(uo)));
            cc = fmaf(sf, cc, si * tg);
            hv = so * tanhf(cc);
        }
        g_hbuf_dec[(t + 1) & 1][b0 + r][jn] = hv;

        __syncthreads();
        int* ctr = &g_ctr_dec[t][btile];
        if (tid == 0) { __threadfence(); atomicAdd(ctr, 1); }
        out[((size_t)(b0 + r) * TT + t) * DD + jn] = hv;   // deferred, overlaps spin
        if (tid == 0) {
            while (*(volatile int*)ctr < 32) { }
            __threadfence();
        }
        __syncthreads();
    }
}

// ---------------- launch ----------------
extern "C" void kernel_launch(void* const* d_in, const int* in_sizes, int n_in,
                              void* d_out, int out_size) {
    const float* x    = (const float*)d_in[0];
    const float* eWih = (const float*)d_in[1];
    const float* eWhh = (const float*)d_in[2];
    const float* ebih = (const float*)d_in[3];
    const float* ebhh = (const float*)d_in[4];
    const float* dWih = (const float*)d_in[5];
    const float* dWhh = (const float*)d_in[6];
    const float* dbih = (const float*)d_in[7];
    const float* dbhh = (const float*)d_in[8];
    float* out = (float*)d_out;

    cudaFuncSetAttribute(enc_rec_kernel,
                         cudaFuncAttributeMaxDynamicSharedMemorySize, ENC_SMEM_BYTES);

    init_kernel<<<64, 256>>>();
    // x_proj_enc = x @ eWih^T + biases : M=65536, N=1024, K=128, Hn=256 (SHIFT=8)
    proj_kernel<128, 8><<<dim3(8, 512), 256>>>(x, eWih, ebih, ebhh, 0, 0, 1024);
    enc_rec_kernel<<<128, 256, ENC_SMEM_BYTES>>>(eWhh);
    // x_proj_dec = encoded @ dWih^T + biases : M=65536, N=512, K=256, Hn=128 (SHIFT=7)
    proj_kernel<256, 7><<<dim3(4, 512), 256>>>(nullptr, dWih, dbih, dbhh, 1, 1, 512);
    dec_rec_kernel<<<128, 256>>>(dWhh, out);
}

// round 13
// speedup vs baseline: 1.2114x; 1.2114x over previous
#include <cuda_runtime.h>

#define BB 256
#define TT 256
#define DD 128
#define HHH 256

typedef unsigned long long u64t;
typedef unsigned int u32t;

// Blackwell packed fp32 ops (PTX-only; ptxas won't emit FFMA2 from C++)
#define FMA2(d,a,b,c) asm("fma.rn.f32x2 %0, %1, %2, %3;" : "=l"(d) : "l"(a), "l"(b), "l"(c))
#define PACK1(d,x)    asm("mov.b64 %0, {%1, %1};" : "=l"(d) : "r"(x))
#define UNPK(lo,hi,v) asm("mov.b64 {%0, %1}, %2;" : "=r"(lo), "=r"(hi) : "l"(v))

#define REL_ADD(p)  asm volatile("red.release.gpu.global.add.s32 [%0], 1;" :: "l"(p) : "memory")
#define ACQ_LD(v,p) asm volatile("ld.acquire.gpu.global.s32 %0, [%1];" : "=r"(v) : "l"(p) : "memory")

// ---------------- scratch (device globals; no allocations) ----------------
__device__ float g_xproj_enc[(size_t)BB * TT * 4 * HHH];  // 256 MB
__device__ float g_xproj_dec[(size_t)BB * TT * 4 * DD];   // 128 MB
__device__ float g_enc_out[(size_t)BB * TT * HHH];        // 64 MB
__device__ float g_hbuf_enc[2][BB][HHH];
__device__ float g_hbuf_dec[2][BB][DD];
__device__ int g_ctr_enc[TT][8];   // per-step, per-btile (16-CTA groups)
__device__ int g_ctr_dec[TT][8];

// ---------------- init: zero h0 buffers + barrier counters ----------------
__global__ void init_kernel() {
    int tid = blockIdx.x * blockDim.x + threadIdx.x;
    int stride = gridDim.x * blockDim.x;
    float* he = &g_hbuf_enc[0][0][0];
    float* hd = &g_hbuf_dec[0][0][0];
    for (int i = tid; i < 2 * BB * HHH; i += stride) he[i] = 0.f;
    for (int i = tid; i < 2 * BB * DD; i += stride) hd[i] = 0.f;
    int* ce = &g_ctr_enc[0][0];
    int* cd = &g_ctr_dec[0][0];
    for (int i = tid; i < TT * 8; i += stride) { ce[i] = 0; cd[i] = 0; }
}

// ---------------- input-projection GEMM: C[M,N] = A[M,K] @ W[N,K]^T + b1 + b2
// 128x128 tiles, BK=8, 256 threads, 8x8 micro-tile, packed f32x2 FMA.
template <int K>
__global__ __launch_bounds__(256) void proj_kernel(
    const float* __restrict__ Ain, const float* __restrict__ W,
    const float* __restrict__ b1, const float* __restrict__ b2,
    int src_sel, int dst_sel, int N)
{
    const float* A = src_sel ? (const float*)g_enc_out : Ain;
    float* C = dst_sel ? (float*)g_xproj_dec : (float*)g_xproj_enc;

    __shared__ float As[8][128];
    __shared__ float Bs[8][128];
    int tid = threadIdx.x;
    int bn = blockIdx.x, bm = blockIdx.y;
    int tr = tid >> 4, tc = tid & 15;   // 16x16 thread grid
    int lr = tid >> 1;                  // stage row 0..127
    int lk = (tid & 1) << 2;            // 0 or 4

    const float* Ag = A + (size_t)(bm * 128 + lr) * K + lk;
    const float* Wg = W + (size_t)(bn * 128 + lr) * K + lk;

    u64t acc[8][4];
#pragma unroll
    for (int i = 0; i < 8; ++i)
#pragma unroll
        for (int j = 0; j < 4; ++j) acc[i][j] = 0ULL;

    for (int kb = 0; kb < K; kb += 8) {
        float4 av = *(const float4*)(Ag + kb);
        float4 wv = *(const float4*)(Wg + kb);
        __syncthreads();
        As[lk + 0][lr] = av.x; As[lk + 1][lr] = av.y;
        As[lk + 2][lr] = av.z; As[lk + 3][lr] = av.w;
        Bs[lk + 0][lr] = wv.x; Bs[lk + 1][lr] = wv.y;
        Bs[lk + 2][lr] = wv.z; Bs[lk + 3][lr] = wv.w;
        __syncthreads();
#pragma unroll
        for (int kk = 0; kk < 8; ++kk) {
            float4 alo = *(const float4*)&As[kk][tr * 4];
            float4 ahi = *(const float4*)&As[kk][64 + tr * 4];
            ulonglong2 wlo = *(const ulonglong2*)&Bs[kk][tc * 4];
            ulonglong2 whi = *(const ulonglong2*)&Bs[kk][64 + tc * 4];
            float ar[8] = {alo.x, alo.y, alo.z, alo.w, ahi.x, ahi.y, ahi.z, ahi.w};
#pragma unroll
            for (int i = 0; i < 8; ++i) {
                u64t a2; PACK1(a2, __float_as_uint(ar[i]));
                FMA2(acc[i][0], a2, wlo.x, acc[i][0]);
                FMA2(acc[i][1], a2, wlo.y, acc[i][1]);
                FMA2(acc[i][2], a2, whi.x, acc[i][2]);
                FMA2(acc[i][3], a2, whi.y, acc[i][3]);
            }
        }
    }
    int c_lo = bn * 128 + tc * 4;
    int c_hi = c_lo + 64;
    float4 v1 = *(const float4*)&b1[c_lo];
    float4 v2 = *(const float4*)&b2[c_lo];
    float4 blo = make_float4(v1.x + v2.x, v1.y + v2.y, v1.z + v2.z, v1.w + v2.w);
    float4 u1 = *(const float4*)&b1[c_hi];
    float4 u2 = *(const float4*)&b2[c_hi];
    float4 bhi = make_float4(u1.x + u2.x, u1.y + u2.y, u1.z + u2.z, u1.w + u2.w);
#pragma unroll
    for (int i = 0; i < 8; ++i) {
        int row = bm * 128 + (i < 4 ? tr * 4 + i : 64 + tr * 4 + (i - 4));
        u32t l0, h0, l1, h1;
        UNPK(l0, h0, acc[i][0]); UNPK(l1, h1, acc[i][1]);
        float4 o0 = make_float4(__uint_as_float(l0) + blo.x, __uint_as_float(h0) + blo.y,
                                __uint_as_float(l1) + blo.z, __uint_as_float(h1) + blo.w);
        *(float4*)&C[(size_t)row * N + c_lo] = o0;
        UNPK(l0, h0, acc[i][2]); UNPK(l1, h1, acc[i][3]);
        float4 o1 = make_float4(__uint_as_float(l0) + bhi.x, __uint_as_float(h0) + bhi.y,
                                __uint_as_float(l1) + bhi.z, __uint_as_float(h1) + bhi.w);
        *(float4*)&C[(size_t)row * N + c_hi] = o1;
    }
}

// ---------------- encoder recurrence: persistent, 128 CTAs ----------------
// CTA = 32 batch rows x 16 neurons (64 gate-cols). 8 btiles x 16 slices.
// Barrier couples only the 16 CTAs sharing a btile.
// smem floats: Ws 256x64=16384, Hs 32x260=8320, Gs 32x68=2176  -> 107520 B
#define ENC_SMEM_BYTES ((16384 + 8320 + 2176) * 4)

__global__ __launch_bounds__(256) void enc_rec_kernel(const float* __restrict__ Whh)
{
    extern __shared__ float sm[];
    float (*Ws)[64]  = (float(*)[64])sm;              // [k][c], c = gate*16+jj
    float (*Hs)[260] = (float(*)[260])(sm + 16384);   // [row][k]
    float (*Gs)[68]  = (float(*)[68])(sm + 16384 + 8320);

    int tid = threadIdx.x;
    int slice = blockIdx.x & 15;   // 16 neuron slices of 16
    int btile = blockIdx.x >> 4;   // 8 batch tiles of 32
    int b0 = btile * 32;
    int j0 = slice * 16;

    { // Ws fill: col c -> Whh row (c>>4)*HHH + j0 + (c&15)
        int c = tid & 63;
        int k0 = (tid >> 6) << 6;   // 4 chunks of 64
        int grow = (c >> 4) * HHH + j0 + (c & 15);
        const float* src = Whh + (size_t)grow * HHH + k0;
#pragma unroll
        for (int kk = 0; kk < 64; ++kk) Ws[k0 + kk][c] = src[kk];
    }
    __syncthreads();

    const int r  = tid >> 3;       // row 0..31
    const int cg = tid & 7;        // col group (8 cols each)
    const int gate = cg >> 1;
    const int jb = j0 + (cg & 1) * 8;        // first of 8 neurons (within gate)
    const float* hrow = &Hs[r][0];
    const float* wbase = &Ws[0][cg * 8];
    const int jj2 = (tid & 7) * 2;           // epilogue: 2 neurons
    float c0 = 0.f, c1 = 0.f;

    for (int t = 0; t < TT; ++t) {
        // xp loads first (hide latency behind staging)
        const float* xp = &g_xproj_enc[((size_t)(b0 + r) * TT + t) * 1024 + gate * HHH + jb];
        ulonglong2 qa = *(const ulonglong2*)xp;
        ulonglong2 qb = *(const ulonglong2*)(xp + 4);

        { // stage h_prev [32][256]
            int k0 = (tid & 7) << 5;
            const float* hp = &g_hbuf_enc[t & 1][b0 + r][k0];
            float* dst = &Hs[r][k0];
#pragma unroll
            for (int kk = 0; kk < 32; kk += 4)
                *(float4*)(dst + kk) = *(const float4*)(hp + kk);
        }
        __syncthreads();

        u64t A0 = qa.x, A1 = qa.y, A2 = qb.x, A3 = qb.y;
#pragma unroll 8
        for (int k = 0; k < HHH; ++k) {
            u64t H;
            PACK1(H, __float_as_uint(hrow[k]));
            const float* wk = wbase + (k << 6);
            ulonglong2 w0 = *(const ulonglong2*)wk;
            ulonglong2 w1 = *(const ulonglong2*)(wk + 4);
            FMA2(A0, H, w0.x, A0); FMA2(A1, H, w0.y, A1);
            FMA2(A2, H, w1.x, A2); FMA2(A3, H, w1.y, A3);
        }
        { // write 8 gate values (two STS.128)
            u64t* gp = (u64t*)&Gs[r][cg * 8];
            gp[0] = A0; gp[1] = A1; gp[2] = A2; gp[3] = A3;
        }
        __syncthreads();

        // epilogue: thread handles neurons jj2, jj2+1 of row r (c in registers)
        float h0v, h1v;
        {
            float vi = Gs[r][jj2],      vf = Gs[r][16 + jj2];
            float vg = Gs[r][32 + jj2], vo = Gs[r][48 + jj2];
            float si = 1.f / (1.f + __expf(-vi));
            float sf = 1.f / (1.f + __expf(-vf));
            float tg = tanhf(vg);
            float so = 1.f / (1.f + __expf(-vo));
            c0 = fmaf(sf, c0, si * tg);
            h0v = so * tanhf(c0);
        }
        {
            float vi = Gs[r][jj2 + 1],      vf = Gs[r][16 + jj2 + 1];
            float vg = Gs[r][32 + jj2 + 1], vo = Gs[r][48 + jj2 + 1];
            float si = 1.f / (1.f + __expf(-vi));
            float sf = 1.f / (1.f + __expf(-vf));
            float tg = tanhf(vg);
            float so = 1.f / (1.f + __expf(-vo));
            c1 = fmaf(sf, c1, si * tg);
            h1v = so * tanhf(c1);
        }
        *(float2*)&g_hbuf_enc[(t + 1) & 1][b0 + r][j0 + jj2] = make_float2(h0v, h1v);

        __syncthreads();   // all h stores issued before release
        int* ctr = &g_ctr_enc[t][btile];
        if (tid == 0) REL_ADD(ctr);
        // deferred enc_out store overlaps the spin
        *(float2*)&g_enc_out[((size_t)(b0 + r) * TT + t) * HHH + j0 + jj2] = make_float2(h0v, h1v);
        if (tid == 0) {
            int v; ACQ_LD(v, ctr);
            while (v < 16) { __nanosleep(32); ACQ_LD(v, ctr); }
        }
        __syncthreads();
    }
}

// ---------------- decoder recurrence: 128 CTAs, 32 rows x 8 neurons ------
__global__ __launch_bounds__(256) void dec_rec_kernel(
    const float* __restrict__ Whh, float* __restrict__ out)
{
    __shared__ float Ws[128][32];   // [k][c], c = gate*8 + jj
    __shared__ float Hs[32][132];
    __shared__ float Gs[32][36];

    int tid = threadIdx.x;
    int slice = blockIdx.x & 15;   // 16 neuron slices of 8
    int btile = blockIdx.x >> 4;   // 8 batch tiles of 32
    int b0 = btile * 32;
    int j0 = slice * 8;

    { // Ws fill
        int c = tid & 31;
        int k0 = (tid >> 5) << 4;   // 8 chunks of 16
        int grow = (c >> 3) * DD + j0 + (c & 7);
        const float* src = Whh + (size_t)grow * DD + k0;
#pragma unroll
        for (int kk = 0; kk < 16; ++kk) Ws[k0 + kk][c] = src[kk];
    }
    __syncthreads();

    const int r  = tid >> 3;       // row 0..31
    const int cg = tid & 7;        // col group (4 cols each)
    const int gate = cg >> 1;
    const int jb = j0 + (cg & 1) * 4;
    const float* hrow = &Hs[r][0];
    const float* wbase = &Ws[0][cg * 4];
    const int jj = tid & 7;        // epilogue: 1 neuron
    float cc = 0.f;

    for (int t = 0; t < TT; ++t) {
        const float* xp = &g_xproj_dec[((size_t)(b0 + r) * TT + t) * 512 + gate * DD + jb];
        ulonglong2 q = *(const ulonglong2*)xp;

        { // stage h_prev [32][128]
            int k0 = (tid & 7) << 4;
            const float* hp = &g_hbuf_dec[t & 1][b0 + r][k0];
            float* dst = &Hs[r][k0];
#pragma unroll
            for (int kk = 0; kk < 16; kk += 4)
                *(float4*)(dst + kk) = *(const float4*)(hp + kk);
        }
        __syncthreads();

        u64t A0 = q.x, A1 = q.y;
#pragma unroll 8
        for (int k = 0; k < DD; ++k) {
            u64t H;
            PACK1(H, __float_as_uint(hrow[k]));
            ulonglong2 w = *(const ulonglong2*)(wbase + (k << 5));
            FMA2(A0, H, w.x, A0);
            FMA2(A1, H, w.y, A1);
        }
        {
            u64t* gp = (u64t*)&Gs[r][cg * 4];
            gp[0] = A0; gp[1] = A1;
        }
        __syncthreads();

        float hv;
        {
            float vi = Gs[r][jj],      vf = Gs[r][8 + jj];
            float vg = Gs[r][16 + jj], vo = Gs[r][24 + jj];
            float si = 1.f / (1.f + __expf(-vi));
            float sf = 1.f / (1.f + __expf(-vf));
            float tg = tanhf(vg);
            float so = 1.f / (1.f + __expf(-vo));
            cc = fmaf(sf, cc, si * tg);
            hv = so * tanhf(cc);
        }
        g_hbuf_dec[(t + 1) & 1][b0 + r][j0 + jj] = hv;

        __syncthreads();
        int* ctr = &g_ctr_dec[t][btile];
        if (tid == 0) REL_ADD(ctr);
        out[((size_t)(b0 + r) * TT + t) * DD + j0 + jj] = hv;   // overlaps spin
        if (tid == 0) {
            int v; ACQ_LD(v, ctr);
            while (v < 16) { __nanosleep(32); ACQ_LD(v, ctr); }
        }
        __syncthreads();
    }
}

// ---------------- launch ----------------
extern "C" void kernel_launch(void* const* d_in, const int* in_sizes, int n_in,
                              void* d_out, int out_size) {
    const float* x    = (const float*)d_in[0];
    const float* eWih = (const float*)d_in[1];
    const float* eWhh = (const float*)d_in[2];
    const float* ebih = (const float*)d_in[3];
    const float* ebhh = (const float*)d_in[4];
    const float* dWih = (const float*)d_in[5];
    const float* dWhh = (const float*)d_in[6];
    const float* dbih = (const float*)d_in[7];
    const float* dbhh = (const float*)d_in[8];
    float* out = (float*)d_out;

    cudaFuncSetAttribute(enc_rec_kernel,
                         cudaFuncAttributeMaxDynamicSharedMemorySize, ENC_SMEM_BYTES);

    init_kernel<<<64, 256>>>();
    // x_proj_enc = x @ eWih^T + biases : M=65536, N=1024, K=128
    proj_kernel<128><<<dim3(8, 512), 256>>>(x, eWih, ebih, ebhh, 0, 0, 1024);
    enc_rec_kernel<<<128, 256, ENC_SMEM_BYTES>>>(eWhh);
    // x_proj_dec = encoded @ dWih^T + biases : M=65536, N=512, K=256
    proj_kernel<256><<<dim3(4, 512), 256>>>(nullptr, dWih, dbih, dbhh, 1, 1, 512);
    dec_rec_kernel<<<128, 256>>>(dWhh, out);
}

// round 14
// speedup vs baseline: 1.6339x; 1.3488x over previous
#include <cuda_runtime.h>

#define BB 256
#define TT 256
#define DD 128
#define HHH 256

typedef unsigned long long u64t;
typedef unsigned int u32t;

// Blackwell packed fp32 ops (PTX-only; ptxas won't emit FFMA2 from C++)
#define FMA2(d,a,b,c) asm("fma.rn.f32x2 %0, %1, %2, %3;" : "=l"(d) : "l"(a), "l"(b), "l"(c))
#define PACK1(d,x)    asm("mov.b64 %0, {%1, %1};" : "=l"(d) : "r"(x))
#define UNPK(lo,hi,v) asm("mov.b64 {%0, %1}, %2;" : "=r"(lo), "=r"(hi) : "l"(v))

// ---------------- scratch (device globals; no allocations) ----------------
__device__ float g_xproj_enc[(size_t)BB * TT * 4 * HHH];  // 256 MB
__device__ float g_xproj_dec[(size_t)BB * TT * 4 * DD];   // 128 MB
__device__ float g_enc_out[(size_t)BB * TT * HHH];        // 64 MB
__device__ float g_hbuf_enc[2][BB][HHH];
__device__ float g_hbuf_dec[2][BB][DD];
__device__ int g_ctr_enc[TT][4];   // per-step, per-btile (32-CTA groups)
__device__ int g_ctr_dec[TT][4];

// ---------------- init: zero h0 buffers + barrier counters ----------------
__global__ void init_kernel() {
    int tid = blockIdx.x * blockDim.x + threadIdx.x;
    int stride = gridDim.x * blockDim.x;
    float* he = &g_hbuf_enc[0][0][0];
    float* hd = &g_hbuf_dec[0][0][0];
    for (int i = tid; i < 2 * BB * HHH; i += stride) he[i] = 0.f;
    for (int i = tid; i < 2 * BB * DD; i += stride) hd[i] = 0.f;
    int* ce = &g_ctr_enc[0][0];
    int* cd = &g_ctr_dec[0][0];
    for (int i = tid; i < TT * 4; i += stride) { ce[i] = 0; cd[i] = 0; }
}

// dummy no-op: shifts enc_rec into the ncu capture slot (user launch #4)
__global__ void dummy_kernel() {}

// ---------------- input-projection GEMM: C[M,N] = A[M,K] @ W[N,K]^T + b1 + b2
// 128x128 tiles, BK=8, 256 threads, 8x8 micro-tile, packed f32x2 FMA.
template <int K>
__global__ __launch_bounds__(256) void proj_kernel(
    const float* __restrict__ Ain, const float* __restrict__ W,
    const float* __restrict__ b1, const float* __restrict__ b2,
    int src_sel, int dst_sel, int N)
{
    const float* A = src_sel ? (const float*)g_enc_out : Ain;
    float* C = dst_sel ? (float*)g_xproj_dec : (float*)g_xproj_enc;

    __shared__ float As[8][128];
    __shared__ float Bs[8][128];
    int tid = threadIdx.x;
    int bn = blockIdx.x, bm = blockIdx.y;
    int tr = tid >> 4, tc = tid & 15;   // 16x16 thread grid
    int lr = tid >> 1;                  // stage row 0..127
    int lk = (tid & 1) << 2;            // 0 or 4

    const float* Ag = A + (size_t)(bm * 128 + lr) * K + lk;
    const float* Wg = W + (size_t)(bn * 128 + lr) * K + lk;

    u64t acc[8][4];
#pragma unroll
    for (int i = 0; i < 8; ++i)
#pragma unroll
        for (int j = 0; j < 4; ++j) acc[i][j] = 0ULL;

    for (int kb = 0; kb < K; kb += 8) {
        float4 av = *(const float4*)(Ag + kb);
        float4 wv = *(const float4*)(Wg + kb);
        __syncthreads();
        As[lk + 0][lr] = av.x; As[lk + 1][lr] = av.y;
        As[lk + 2][lr] = av.z; As[lk + 3][lr] = av.w;
        Bs[lk + 0][lr] = wv.x; Bs[lk + 1][lr] = wv.y;
        Bs[lk + 2][lr] = wv.z; Bs[lk + 3][lr] = wv.w;
        __syncthreads();
#pragma unroll
        for (int kk = 0; kk < 8; ++kk) {
            float4 alo = *(const float4*)&As[kk][tr * 4];
            float4 ahi = *(const float4*)&As[kk][64 + tr * 4];
            ulonglong2 wlo = *(const ulonglong2*)&Bs[kk][tc * 4];
            ulonglong2 whi = *(const ulonglong2*)&Bs[kk][64 + tc * 4];
            float ar[8] = {alo.x, alo.y, alo.z, alo.w, ahi.x, ahi.y, ahi.z, ahi.w};
#pragma unroll
            for (int i = 0; i < 8; ++i) {
                u64t a2; PACK1(a2, __float_as_uint(ar[i]));
                FMA2(acc[i][0], a2, wlo.x, acc[i][0]);
                FMA2(acc[i][1], a2, wlo.y, acc[i][1]);
                FMA2(acc[i][2], a2, whi.x, acc[i][2]);
                FMA2(acc[i][3], a2, whi.y, acc[i][3]);
            }
        }
    }
    int c_lo = bn * 128 + tc * 4;
    int c_hi = c_lo + 64;
    float4 v1 = *(const float4*)&b1[c_lo];
    float4 v2 = *(const float4*)&b2[c_lo];
    float4 blo = make_float4(v1.x + v2.x, v1.y + v2.y, v1.z + v2.z, v1.w + v2.w);
    float4 u1 = *(const float4*)&b1[c_hi];
    float4 u2 = *(const float4*)&b2[c_hi];
    float4 bhi = make_float4(u1.x + u2.x, u1.y + u2.y, u1.z + u2.z, u1.w + u2.w);
#pragma unroll
    for (int i = 0; i < 8; ++i) {
        int row = bm * 128 + (i < 4 ? tr * 4 + i : 64 + tr * 4 + (i - 4));
        u32t l0, h0, l1, h1;
        UNPK(l0, h0, acc[i][0]); UNPK(l1, h1, acc[i][1]);
        float4 o0 = make_float4(__uint_as_float(l0) + blo.x, __uint_as_float(h0) + blo.y,
                                __uint_as_float(l1) + blo.z, __uint_as_float(h1) + blo.w);
        *(float4*)&C[(size_t)row * N + c_lo] = o0;
        UNPK(l0, h0, acc[i][2]); UNPK(l1, h1, acc[i][3]);
        float4 o1 = make_float4(__uint_as_float(l0) + bhi.x, __uint_as_float(h0) + bhi.y,
                                __uint_as_float(l1) + bhi.z, __uint_as_float(h1) + bhi.w);
        *(float4*)&C[(size_t)row * N + c_hi] = o1;
    }
}

// ---------------- encoder recurrence: persistent, 128 CTAs ----------------
// CTA = 64 batch rows x 8 neurons (32 gate-cols). Whh slice in smem once.
// Barrier only among the 32 CTAs sharing a batch tile.
#define ENC_SMEM_BYTES ((8192 + 16640 + 2112 + 512) * 4)

__global__ __launch_bounds__(256) void enc_rec_kernel(const float* __restrict__ Whh)
{
    extern __shared__ float sm[];
    float (*Ws)[32]  = (float(*)[32])sm;
    float (*Hs)[260] = (float(*)[260])(sm + 8192);
    float (*Gs)[33]  = (float(*)[33])(sm + 8192 + 16640);
    float (*Cs)[8]   = (float(*)[8])(sm + 8192 + 16640 + 2112);

    int tid = threadIdx.x;
    int slice = blockIdx.x & 31;   // 0..31 (neuron slices of 8)
    int btile = blockIdx.x >> 5;   // 0..3  (batch tiles of 64)
    int b0 = btile * 64;
    int j0 = slice * 8;

    // load Whh slice transposed: Ws[k][c], c = gate*8 + jj
    {
        int c = tid & 31;
        int k0 = (tid >> 5) << 5;
        int grow = (c >> 3) * HHH + j0 + (c & 7);
        const float* src = Whh + (size_t)grow * HHH + k0;
#pragma unroll
        for (int kk = 0; kk < 32; ++kk) Ws[k0 + kk][c] = src[kk];
    }
    for (int i = tid; i < 512; i += 256) ((float*)Cs)[i] = 0.f;
    __syncthreads();

    const int tr2 = (tid >> 3) << 1;                     // row pair 0..62
    const int tc4 = (tid & 7) << 2;                      // col quad 0..28
    const int gci = (tc4 >> 3) * HHH + j0 + (tc4 & 7);   // global gate col
    const float* hr0 = &Hs[tr2][0];
    const float* hr1 = &Hs[tr2 + 1][0];
    const float* wcol = &Ws[0][tc4];

    for (int t = 0; t < TT; ++t) {
        { // stage h_prev tile [64][256] from global double buffer
            int r = tid >> 2;
            int k0 = (tid & 3) << 6;
            const float* hp = &g_hbuf_enc[t & 1][b0 + r][k0];
            float* dst = &Hs[r][k0];
#pragma unroll
            for (int kk = 0; kk < 64; kk += 4)
                *(float4*)(dst + kk) = *(const float4*)(hp + kk);
        }
        __syncthreads();

        const float* xp0 = &g_xproj_enc[((size_t)(b0 + tr2) * TT + t) * 1024 + gci];
        ulonglong2 q0 = *(const ulonglong2*)xp0;
        ulonglong2 q1 = *(const ulonglong2*)(xp0 + (size_t)TT * 1024);
        u64t A00 = q0.x, A01 = q0.y, A10 = q1.x, A11 = q1.y;
#pragma unroll 8
        for (int k = 0; k < HHH; ++k) {
            u64t H0, H1;
            PACK1(H0, __float_as_uint(hr0[k]));
            PACK1(H1, __float_as_uint(hr1[k]));
            ulonglong2 w = *(const ulonglong2*)(wcol + (k << 5));
            FMA2(A00, H0, w.x, A00); FMA2(A01, H0, w.y, A01);
            FMA2(A10, H1, w.x, A10); FMA2(A11, H1, w.y, A11);
        }
        {
            u32t l, h;
            UNPK(l, h, A00); Gs[tr2][tc4 + 0] = __uint_as_float(l); Gs[tr2][tc4 + 1] = __uint_as_float(h);
            UNPK(l, h, A01); Gs[tr2][tc4 + 2] = __uint_as_float(l); Gs[tr2][tc4 + 3] = __uint_as_float(h);
            UNPK(l, h, A10); Gs[tr2 + 1][tc4 + 0] = __uint_as_float(l); Gs[tr2 + 1][tc4 + 1] = __uint_as_float(h);
            UNPK(l, h, A11); Gs[tr2 + 1][tc4 + 2] = __uint_as_float(l); Gs[tr2 + 1][tc4 + 3] = __uint_as_float(h);
        }
        __syncthreads();

        float hsave[2];
#pragma unroll
        for (int q = 0; q < 2; ++q) {
            int p = tid + q * 256;
            int r = p >> 3, j = p & 7;
            float vi = Gs[r][j], vf = Gs[r][8 + j], vg = Gs[r][16 + j], vo = Gs[r][24 + j];
            float si = 1.f / (1.f + __expf(-vi));
            float sf = 1.f / (1.f + __expf(-vf));
            float tg = tanhf(vg);
            float so = 1.f / (1.f + __expf(-vo));
            float cv = fmaf(sf, Cs[r][j], si * tg);
            Cs[r][j] = cv;
            float h = so * tanhf(cv);
            g_hbuf_enc[(t + 1) & 1][b0 + r][j0 + j] = h;
            hsave[q] = h;
        }
        __syncthreads();                       // all h stores issued (happens-before tid0)
        int* ctr = &g_ctr_enc[t][btile];
        if (tid == 0) { __threadfence(); atomicAdd(ctr, 1); }   // single-thread release
        // deferred enc_out stores overlap the spin
#pragma unroll
        for (int q = 0; q < 2; ++q) {
            int p = tid + q * 256;
            int r = p >> 3, j = p & 7;
            g_enc_out[((size_t)(b0 + r) * TT + t) * HHH + j0 + j] = hsave[q];
        }
        if (tid == 0) {
            while (*(volatile int*)ctr < 32) __nanosleep(32);
            __threadfence();
        }
        __syncthreads();
    }
}

// ---------------- decoder recurrence: 128 CTAs, 64 rows x 4 neurons ------
__global__ __launch_bounds__(256) void dec_rec_kernel(
    const float* __restrict__ Whh, float* __restrict__ out)
{
    __shared__ float Ws[128][16];
    __shared__ float Hs[64][132];
    __shared__ float Gs[64][17];
    __shared__ float Cs[64][4];

    int tid = threadIdx.x;
    int slice = blockIdx.x & 31;   // 0..31 (neuron slices of 4)
    int btile = blockIdx.x >> 5;   // 0..3
    int b0 = btile * 64;
    int j0 = slice * 4;

    {
        int c = tid & 15;
        int k0 = (tid >> 4) << 3;
        int grow = (c >> 2) * DD + j0 + (c & 3);
        const float* src = Whh + (size_t)grow * DD + k0;
#pragma unroll
        for (int kk = 0; kk < 8; ++kk) Ws[k0 + kk][c] = src[kk];
    }
    if (tid < 256) ((float*)Cs)[tid] = 0.f;
    __syncthreads();

    const int tr2 = (tid >> 3) << 1;
    const int tc2 = (tid & 7) << 1;
    const int gci = (tc2 >> 2) * DD + j0 + (tc2 & 3);
    const float* hr0 = &Hs[tr2][0];
    const float* hr1 = &Hs[tr2 + 1][0];
    const float* wcol = &Ws[0][tc2];

    for (int t = 0; t < TT; ++t) {
        {
            int r = tid >> 2;
            int k0 = (tid & 3) << 5;
            const float* hp = &g_hbuf_dec[t & 1][b0 + r][k0];
            float* dst = &Hs[r][k0];
#pragma unroll
            for (int kk = 0; kk < 32; kk += 4)
                *(float4*)(dst + kk) = *(const float4*)(hp + kk);
        }
        __syncthreads();

        const float* xp0 = &g_xproj_dec[((size_t)(b0 + tr2) * TT + t) * 512 + gci];
        u64t A0 = *(const u64t*)xp0;
        u64t A1 = *(const u64t*)(xp0 + (size_t)TT * 512);
#pragma unroll 8
        for (int k = 0; k < DD; ++k) {
            u64t H0, H1;
            PACK1(H0, __float_as_uint(hr0[k]));
            PACK1(H1, __float_as_uint(hr1[k]));
            u64t w = *(const u64t*)(wcol + (k << 4));
            FMA2(A0, H0, w, A0);
            FMA2(A1, H1, w, A1);
        }
        {
            u32t l, h;
            UNPK(l, h, A0); Gs[tr2][tc2] = __uint_as_float(l); Gs[tr2][tc2 + 1] = __uint_as_float(h);
            UNPK(l, h, A1); Gs[tr2 + 1][tc2] = __uint_as_float(l); Gs[tr2 + 1][tc2 + 1] = __uint_as_float(h);
        }
        __syncthreads();

        float hsave;
        int r = tid >> 2, j = tid & 3;
        {
            float vi = Gs[r][j], vf = Gs[r][4 + j], vg = Gs[r][8 + j], vo = Gs[r][12 + j];
            float si = 1.f / (1.f + __expf(-vi));
            float sf = 1.f / (1.f + __expf(-vf));
            float tg = tanhf(vg);
            float so = 1.f / (1.f + __expf(-vo));
            float cv = fmaf(sf, Cs[r][j], si * tg);
            Cs[r][j] = cv;
            hsave = so * tanhf(cv);
            g_hbuf_dec[(t + 1) & 1][b0 + r][j0 + j] = hsave;
        }
        __syncthreads();                       // happens-before tid0's fence
        int* ctr = &g_ctr_dec[t][btile];
        if (tid == 0) { __threadfence(); atomicAdd(ctr, 1); }
        out[((size_t)(b0 + r) * TT + t) * DD + j0 + j] = hsave;   // overlaps spin
        if (tid == 0) {
            while (*(volatile int*)ctr < 32) __nanosleep(32);
            __threadfence();
        }
        __syncthreads();
    }
}

// ---------------- launch ----------------
extern "C" void kernel_launch(void* const* d_in, const int* in_sizes, int n_in,
                              void* d_out, int out_size) {
    const float* x    = (const float*)d_in[0];
    const float* eWih = (const float*)d_in[1];
    const float* eWhh = (const float*)d_in[2];
    const float* ebih = (const float*)d_in[3];
    const float* ebhh = (const float*)d_in[4];
    const float* dWih = (const float*)d_in[5];
    const float* dWhh = (const float*)d_in[6];
    const float* dbih = (const float*)d_in[7];
    const float* dbhh = (const float*)d_in[8];
    float* out = (float*)d_out;

    cudaFuncSetAttribute(enc_rec_kernel,
                         cudaFuncAttributeMaxDynamicSharedMemorySize, ENC_SMEM_BYTES);

    init_kernel<<<64, 256>>>();
    // x_proj_enc = x @ eWih^T + biases : M=65536, N=1024, K=128
    proj_kernel<128><<<dim3(8, 512), 256>>>(x, eWih, ebih, ebhh, 0, 0, 1024);
    dummy_kernel<<<1, 32>>>();   // shifts enc_rec into ncu's capture slot
    enc_rec_kernel<<<128, 256, ENC_SMEM_BYTES>>>(eWhh);
    // x_proj_dec = encoded @ dWih^T + biases : M=65536, N=512, K=256
    proj_kernel<256><<<dim3(4, 512), 256>>>(nullptr, dWih, dbih, dbhh, 1, 1, 512);
    dec_rec_kernel<<<128, 256>>>(dWhh, out);
}